// round 6
// baseline (speedup 1.0000x reference)
#include <cuda_runtime.h>
#include <cuda_fp16.h>
#include <cstdint>

#define M_DIM 4096
#define N_DIM 8192
#define K_DIM 2048

#define BM 128
#define BN 256
#define BK 64
#define NIT (K_DIM / BK)      // 32
#define NSTAGE 3
#define LDS 72                          // halves per smem row (144B; 4*dr mod 32 distinct -> ldsm conflict-free)
#define A_HALVES (BM * LDS)             // 9216
#define B_HALVES (BN * LDS)             // 18432
#define STAGE_HALVES (A_HALVES + B_HALVES)  // 27648 (55296 B)
#define SMEM_BYTES (NSTAGE * STAGE_HALVES * 2)  // 165888

// Static scratch (allocation-free rule): fp16 weights + fp16 activations
__device__ __align__(16) __half g_w[(size_t)N_DIM * K_DIM];  // 32 MB
__device__ __align__(16) __half g_x[(size_t)M_DIM * K_DIM];  // 16 MB

__constant__ float c_lut[16] = {
    -1.0f, -0.5f, -0.333333f, -0.2f, -0.142857f, -0.090909f, -0.076923f,
    0.0f, 0.076923f, 0.090909f, 0.142857f, 0.2f, 0.333333f, 0.5f, 1.0f, 0.0f};

// ---------------------------------------------------------------------------
// Dequant: smem LUT (16 words -> 16 distinct banks, broadcast on repeats)
// ---------------------------------------------------------------------------
__global__ __launch_bounds__(256) void dequant_kernel(const int* __restrict__ gi,
                                                      const float* __restrict__ scale_p) {
    __shared__ float lut[16];
    if (threadIdx.x < 16) lut[threadIdx.x] = c_lut[threadIdx.x] * (*scale_p);
    __syncthreads();
    size_t t = (size_t)blockIdx.x * blockDim.x + threadIdx.x;
    const int4* gp = reinterpret_cast<const int4*>(gi) + t * 2;
    int4 a = gp[0];
    int4 b = gp[1];
    __half2 h0 = __floats2half2_rn(lut[a.x], lut[a.y]);
    __half2 h1 = __floats2half2_rn(lut[a.z], lut[a.w]);
    __half2 h2 = __floats2half2_rn(lut[b.x], lut[b.y]);
    __half2 h3 = __floats2half2_rn(lut[b.z], lut[b.w]);
    uint4 o;
    o.x = *reinterpret_cast<uint32_t*>(&h0);
    o.y = *reinterpret_cast<uint32_t*>(&h1);
    o.z = *reinterpret_cast<uint32_t*>(&h2);
    o.w = *reinterpret_cast<uint32_t*>(&h3);
    *reinterpret_cast<uint4*>(g_w + t * 8) = o;
}

// ---------------------------------------------------------------------------
// Convert activations fp32 -> fp16, 8 per thread
// ---------------------------------------------------------------------------
__global__ __launch_bounds__(256) void xconv_kernel(const float* __restrict__ x) {
    size_t t = (size_t)blockIdx.x * blockDim.x + threadIdx.x;
    const float4* xp = reinterpret_cast<const float4*>(x) + t * 2;
    float4 a = xp[0];
    float4 b = xp[1];
    __half2 h0 = __floats2half2_rn(a.x, a.y);
    __half2 h1 = __floats2half2_rn(a.z, a.w);
    __half2 h2 = __floats2half2_rn(b.x, b.y);
    __half2 h3 = __floats2half2_rn(b.z, b.w);
    uint4 o;
    o.x = *reinterpret_cast<uint32_t*>(&h0);
    o.y = *reinterpret_cast<uint32_t*>(&h1);
    o.z = *reinterpret_cast<uint32_t*>(&h2);
    o.w = *reinterpret_cast<uint32_t*>(&h3);
    *reinterpret_cast<uint4*>(g_x + t * 8) = o;
}

// ---------------------------------------------------------------------------
// helpers
// ---------------------------------------------------------------------------
__device__ __forceinline__ void cp16(__half* dst, const __half* src) {
    uint32_t d = (uint32_t)__cvta_generic_to_shared(dst);
    asm volatile("cp.async.cg.shared.global [%0], [%1], 16;\n" :: "r"(d), "l"(src));
}

__device__ __forceinline__ void ldsm4(uint32_t* r, const __half* p) {
    uint32_t a = (uint32_t)__cvta_generic_to_shared(p);
    asm volatile("ldmatrix.sync.aligned.m8n8.x4.shared.b16 {%0,%1,%2,%3}, [%4];\n"
                 : "=r"(r[0]), "=r"(r[1]), "=r"(r[2]), "=r"(r[3]) : "r"(a));
}

__device__ __forceinline__ void mma16816(float* c, const uint32_t* a, const uint32_t* b) {
    asm volatile(
        "mma.sync.aligned.m16n8k16.row.col.f32.f16.f16.f32 "
        "{%0,%1,%2,%3}, {%4,%5,%6,%7}, {%8,%9}, {%0,%1,%2,%3};\n"
        : "+f"(c[0]), "+f"(c[1]), "+f"(c[2]), "+f"(c[3])
        : "r"(a[0]), "r"(a[1]), "r"(a[2]), "r"(a[3]), "r"(b[0]), "r"(b[1]));
}

// ---------------------------------------------------------------------------
// GEMM: out[M,N] = g_x[M,K] @ g_w[N,K]^T
// CTA 128x256x64, 256 threads, 8 warps (2M x 4N), warp tile 64x64.
// 3-stage cp.async pipeline, 1 sync per BK=64, register-double-buffered
// fragments so ldsm of step k+1 overlaps the 32 MMAs of step k.
// ---------------------------------------------------------------------------
__global__ __launch_bounds__(256, 1) void gemm_kernel(float* __restrict__ out) {
    extern __shared__ __half sm[];

    const int tid = threadIdx.x;
    const int warp = tid >> 5;
    const int lane = tid & 31;
    const int wm = warp >> 2;     // 0..1 : 64-row slice
    const int wn = warp & 3;      // 0..3 : 64-col slice
    const int m0 = blockIdx.y * BM;
    const int n0 = blockIdx.x * BN;

    // global->smem copy mapping
    const int ar = tid >> 1;                 // A row 0..127
    const int ac = (tid & 1) * 32;           // A col base (halves)
    const int br = tid;                      // B row 0..255

    float acc[4][8][4];
#pragma unroll
    for (int i = 0; i < 4; i++)
#pragma unroll
        for (int j = 0; j < 8; j++)
#pragma unroll
            for (int k = 0; k < 4; k++) acc[i][j][k] = 0.0f;

    auto load_stage = [&](int s, int k0) {
        __half* a = sm + s * STAGE_HALVES;
        __half* b = a + A_HALVES;
        const __half* ga = g_x + (size_t)(m0 + ar) * K_DIM + k0 + ac;
#pragma unroll
        for (int j = 0; j < 4; j++)
            cp16(a + ar * LDS + ac + j * 8, ga + j * 8);
        const __half* gb = g_w + (size_t)(n0 + br) * K_DIM + k0;
#pragma unroll
        for (int j = 0; j < 8; j++)
            cp16(b + br * LDS + j * 8, gb + j * 8);
        asm volatile("cp.async.commit_group;\n");
    };

    // fragment loader for one k-step (16 halves starting at kk)
    auto load_frags = [&](const __half* a_s, const __half* b_s, int kk,
                          uint32_t af[4][4], uint32_t bf[8][2]) {
#pragma unroll
        for (int mt = 0; mt < 4; mt++) {
            const __half* p = a_s + (wm * 64 + mt * 16 + (lane & 15)) * LDS
                                  + kk + (lane >> 4) * 8;
            ldsm4(af[mt], p);
        }
#pragma unroll
        for (int np = 0; np < 4; np++) {
            const __half* p = b_s + (wn * 64 + np * 16 + (lane & 7) + ((lane >> 4) & 1) * 8) * LDS
                                  + kk + ((lane >> 3) & 1) * 8;
            uint32_t r[4];
            ldsm4(r, p);
            bf[np * 2][0] = r[0]; bf[np * 2][1] = r[1];
            bf[np * 2 + 1][0] = r[2]; bf[np * 2 + 1][1] = r[3];
        }
    };

    // prologue: 2 stages in flight
    load_stage(0, 0);
    load_stage(1, BK);

    uint32_t af[2][4][4];
    uint32_t bf[2][8][2];

    for (int it = 0; it < NIT; ++it) {
        asm volatile("cp.async.wait_group 1;\n");
        __syncthreads();   // stage `it` visible; all warps done with stage it-1

        if (it + 2 < NIT) load_stage((it + 2) % NSTAGE, (it + 2) * BK);

        const __half* a_s = sm + (it % NSTAGE) * STAGE_HALVES;
        const __half* b_s = a_s + A_HALVES;

        load_frags(a_s, b_s, 0, af[0], bf[0]);
#pragma unroll
        for (int ks = 0; ks < 4; ks++) {
            int cur = ks & 1;
            if (ks < 3) load_frags(a_s, b_s, (ks + 1) * 16, af[cur ^ 1], bf[cur ^ 1]);
#pragma unroll
            for (int mt = 0; mt < 4; mt++)
#pragma unroll
                for (int nt = 0; nt < 8; nt++)
                    mma16816(acc[mt][nt], af[cur][mt], bf[cur][nt]);
        }
    }

    // epilogue: direct fp32 stores
#pragma unroll
    for (int mt = 0; mt < 4; mt++) {
#pragma unroll
        for (int nt = 0; nt < 8; nt++) {
            int row = m0 + wm * 64 + mt * 16 + (lane >> 2);
            int col = n0 + wn * 64 + nt * 8 + (lane & 3) * 2;
            float2 v0 = make_float2(acc[mt][nt][0], acc[mt][nt][1]);
            float2 v1 = make_float2(acc[mt][nt][2], acc[mt][nt][3]);
            *reinterpret_cast<float2*>(out + (size_t)row * N_DIM + col) = v0;
            *reinterpret_cast<float2*>(out + (size_t)(row + 8) * N_DIM + col) = v1;
        }
    }
}

// ---------------------------------------------------------------------------
// kernel_launch
// ---------------------------------------------------------------------------
extern "C" void kernel_launch(void* const* d_in, const int* in_sizes, int n_in,
                              void* d_out, int out_size) {
    const float* x = (const float*)d_in[0];
    const int* gi = (const int*)d_in[1];
    const float* scale = (const float*)d_in[2];
    float* out = (float*)d_out;

    dequant_kernel<<<(N_DIM * (K_DIM / 8)) / 256, 256>>>(gi, scale);   // 8192 blocks
    xconv_kernel<<<(M_DIM * (K_DIM / 8)) / 256, 256>>>(x);             // 4096 blocks

    cudaFuncSetAttribute(gemm_kernel, cudaFuncAttributeMaxDynamicSharedMemorySize, SMEM_BYTES);
    dim3 grid(N_DIM / BN, M_DIM / BM);  // (32, 32)
    gemm_kernel<<<grid, 256, SMEM_BYTES>>>(out);
}

// round 7
// speedup vs baseline: 1.3310x; 1.3310x over previous
#include <cuda_runtime.h>
#include <cuda_fp16.h>
#include <cstdint>

#define M_DIM 4096
#define N_DIM 8192
#define K_DIM 2048

#define BM 128
#define BN 128
#define BK 64
#define NIT (K_DIM / BK)      // 32
#define NSTAGE 3
// smem: 128B rows (64 halves), XOR-swizzled, no padding
#define ROW_HALVES 64
#define A_HALVES (BM * ROW_HALVES)          // 8192
#define B_HALVES (BN * ROW_HALVES)          // 8192
#define STAGE_HALVES (A_HALVES + B_HALVES)  // 16384 (32 KB)
#define SMEM_BYTES (NSTAGE * STAGE_HALVES * 2)  // 98304 -> 2 CTAs/SM (192 KB)

// Static scratch (allocation-free rule): fp16 weights + fp16 activations
__device__ __align__(16) __half g_w[(size_t)N_DIM * K_DIM];  // 32 MB
__device__ __align__(16) __half g_x[(size_t)M_DIM * K_DIM];  // 16 MB

__constant__ float c_lut[16] = {
    -1.0f, -0.5f, -0.333333f, -0.2f, -0.142857f, -0.090909f, -0.076923f,
    0.0f, 0.076923f, 0.090909f, 0.142857f, 0.2f, 0.333333f, 0.5f, 1.0f, 0.0f};

// ---------------------------------------------------------------------------
// Dequant: smem LUT (16 words -> 16 distinct banks, broadcast on repeats)
// ---------------------------------------------------------------------------
__global__ __launch_bounds__(256) void dequant_kernel(const int* __restrict__ gi,
                                                      const float* __restrict__ scale_p) {
    __shared__ float lut[16];
    if (threadIdx.x < 16) lut[threadIdx.x] = c_lut[threadIdx.x] * (*scale_p);
    __syncthreads();
    size_t t = (size_t)blockIdx.x * blockDim.x + threadIdx.x;
    const int4* gp = reinterpret_cast<const int4*>(gi) + t * 2;
    int4 a = gp[0];
    int4 b = gp[1];
    __half2 h0 = __floats2half2_rn(lut[a.x], lut[a.y]);
    __half2 h1 = __floats2half2_rn(lut[a.z], lut[a.w]);
    __half2 h2 = __floats2half2_rn(lut[b.x], lut[b.y]);
    __half2 h3 = __floats2half2_rn(lut[b.z], lut[b.w]);
    uint4 o;
    o.x = *reinterpret_cast<uint32_t*>(&h0);
    o.y = *reinterpret_cast<uint32_t*>(&h1);
    o.z = *reinterpret_cast<uint32_t*>(&h2);
    o.w = *reinterpret_cast<uint32_t*>(&h3);
    *reinterpret_cast<uint4*>(g_w + t * 8) = o;
}

// ---------------------------------------------------------------------------
// Convert activations fp32 -> fp16, 8 per thread
// ---------------------------------------------------------------------------
__global__ __launch_bounds__(256) void xconv_kernel(const float* __restrict__ x) {
    size_t t = (size_t)blockIdx.x * blockDim.x + threadIdx.x;
    const float4* xp = reinterpret_cast<const float4*>(x) + t * 2;
    float4 a = xp[0];
    float4 b = xp[1];
    __half2 h0 = __floats2half2_rn(a.x, a.y);
    __half2 h1 = __floats2half2_rn(a.z, a.w);
    __half2 h2 = __floats2half2_rn(b.x, b.y);
    __half2 h3 = __floats2half2_rn(b.z, b.w);
    uint4 o;
    o.x = *reinterpret_cast<uint32_t*>(&h0);
    o.y = *reinterpret_cast<uint32_t*>(&h1);
    o.z = *reinterpret_cast<uint32_t*>(&h2);
    o.w = *reinterpret_cast<uint32_t*>(&h3);
    *reinterpret_cast<uint4*>(g_x + t * 8) = o;
}

// ---------------------------------------------------------------------------
// helpers
// ---------------------------------------------------------------------------
__device__ __forceinline__ void cp16(__half* dst, const __half* src) {
    uint32_t d = (uint32_t)__cvta_generic_to_shared(dst);
    asm volatile("cp.async.cg.shared.global [%0], [%1], 16;\n" :: "r"(d), "l"(src));
}

__device__ __forceinline__ void ldsm4(uint32_t* r, const __half* p) {
    uint32_t a = (uint32_t)__cvta_generic_to_shared(p);
    asm volatile("ldmatrix.sync.aligned.m8n8.x4.shared.b16 {%0,%1,%2,%3}, [%4];\n"
                 : "=r"(r[0]), "=r"(r[1]), "=r"(r[2]), "=r"(r[3]) : "r"(a));
}

__device__ __forceinline__ void mma16816(float* c, const uint32_t* a, const uint32_t* b) {
    asm volatile(
        "mma.sync.aligned.m16n8k16.row.col.f32.f16.f16.f32 "
        "{%0,%1,%2,%3}, {%4,%5,%6,%7}, {%8,%9}, {%0,%1,%2,%3};\n"
        : "+f"(c[0]), "+f"(c[1]), "+f"(c[2]), "+f"(c[3])
        : "r"(a[0]), "r"(a[1]), "r"(a[2]), "r"(a[3]), "r"(b[0]), "r"(b[1]));
}

// swizzled address: row (128B rows), 16B-chunk index. phys chunk = chunk ^ (row & 7)
__device__ __forceinline__ const __half* swz(const __half* base, int row, int chunk) {
    return base + row * ROW_HALVES + ((chunk ^ (row & 7)) << 3);
}
__device__ __forceinline__ __half* swzw(__half* base, int row, int chunk) {
    return base + row * ROW_HALVES + ((chunk ^ (row & 7)) << 3);
}

// ---------------------------------------------------------------------------
// GEMM: out[M,N] = g_x[M,K] @ g_w[N,K]^T
// CTA 128x128x64, 256 threads, 8 warps (4M x 2N), warp tile 32x64.
// 3-stage cp.async pipeline, XOR-swizzled smem, ONE __syncthreads per iter,
// 2 CTAs/SM for latency hiding.
// ---------------------------------------------------------------------------
__global__ __launch_bounds__(256, 2) void gemm_kernel(float* __restrict__ out) {
    extern __shared__ __half sm[];

    const int tid = threadIdx.x;
    const int warp = tid >> 5;
    const int lane = tid & 31;
    const int wm = warp & 3;   // 0..3 : 32-row slice
    const int wn = warp >> 2;  // 0..1 : 64-col slice
    const int m0 = blockIdx.y * BM;
    const int n0 = blockIdx.x * BN;

    // copy mapping: 1024 chunks per tile (128 rows x 8 chunks), 4 per thread
    const int crow = tid >> 1;           // 0..127 (2 threads per row)
    const int cchk = (tid & 1) * 4;      // chunks 0-3 or 4-7

    float acc[2][8][4];
#pragma unroll
    for (int i = 0; i < 2; i++)
#pragma unroll
        for (int j = 0; j < 8; j++)
#pragma unroll
            for (int k = 0; k < 4; k++) acc[i][j][k] = 0.0f;

    auto load_stage = [&](int s, int k0) {
        __half* a = sm + s * STAGE_HALVES;
        __half* b = a + A_HALVES;
        const __half* ga = g_x + (size_t)(m0 + crow) * K_DIM + k0 + cchk * 8;
        const __half* gb = g_w + (size_t)(n0 + crow) * K_DIM + k0 + cchk * 8;
#pragma unroll
        for (int j = 0; j < 4; j++) {
            cp16(swzw(a, crow, cchk + j), ga + j * 8);
            cp16(swzw(b, crow, cchk + j), gb + j * 8);
        }
        asm volatile("cp.async.commit_group;\n");
    };

    load_stage(0, 0);
    load_stage(1, BK);

    for (int it = 0; it < NIT; ++it) {
        asm volatile("cp.async.wait_group 1;\n");
        __syncthreads();   // stage `it` visible; all warps done with stage it-1

        if (it + 2 < NIT) load_stage((it + 2) % NSTAGE, (it + 2) * BK);

        const __half* a_s = sm + (it % NSTAGE) * STAGE_HALVES;
        const __half* b_s = a_s + A_HALVES;

#pragma unroll
        for (int ks = 0; ks < 4; ks++) {
            const int kc = ks * 2;  // base 16B-chunk of this k-step
            uint32_t af[2][4];
#pragma unroll
            for (int mt = 0; mt < 2; mt++)
                ldsm4(af[mt], swz(a_s, wm * 32 + mt * 16 + (lane & 15), kc + (lane >> 4)));
            uint32_t bf[8][2];
#pragma unroll
            for (int np = 0; np < 4; np++) {
                uint32_t r[4];
                ldsm4(r, swz(b_s, wn * 64 + np * 16 + (lane & 7) + ((lane >> 4) & 1) * 8,
                             kc + ((lane >> 3) & 1)));
                bf[np * 2][0] = r[0]; bf[np * 2][1] = r[1];
                bf[np * 2 + 1][0] = r[2]; bf[np * 2 + 1][1] = r[3];
            }
#pragma unroll
            for (int mt = 0; mt < 2; mt++)
#pragma unroll
                for (int nt = 0; nt < 8; nt++)
                    mma16816(acc[mt][nt], af[mt], bf[nt]);
        }
    }

    // epilogue: direct fp32 stores
#pragma unroll
    for (int mt = 0; mt < 2; mt++) {
#pragma unroll
        for (int nt = 0; nt < 8; nt++) {
            int row = m0 + wm * 32 + mt * 16 + (lane >> 2);
            int col = n0 + wn * 64 + nt * 8 + (lane & 3) * 2;
            float2 v0 = make_float2(acc[mt][nt][0], acc[mt][nt][1]);
            float2 v1 = make_float2(acc[mt][nt][2], acc[mt][nt][3]);
            *reinterpret_cast<float2*>(out + (size_t)row * N_DIM + col) = v0;
            *reinterpret_cast<float2*>(out + (size_t)(row + 8) * N_DIM + col) = v1;
        }
    }
}

// ---------------------------------------------------------------------------
// kernel_launch
// ---------------------------------------------------------------------------
extern "C" void kernel_launch(void* const* d_in, const int* in_sizes, int n_in,
                              void* d_out, int out_size) {
    const float* x = (const float*)d_in[0];
    const int* gi = (const int*)d_in[1];
    const float* scale = (const float*)d_in[2];
    float* out = (float*)d_out;

    dequant_kernel<<<(N_DIM * (K_DIM / 8)) / 256, 256>>>(gi, scale);   // 8192 blocks
    xconv_kernel<<<(M_DIM * (K_DIM / 8)) / 256, 256>>>(x);             // 4096 blocks

    cudaFuncSetAttribute(gemm_kernel, cudaFuncAttributeMaxDynamicSharedMemorySize, SMEM_BYTES);
    dim3 grid(N_DIM / BN, M_DIM / BM);  // (64, 32)
    gemm_kernel<<<grid, 256, SMEM_BYTES>>>(out);
}